// round 10
// baseline (speedup 1.0000x reference)
#include <cuda_runtime.h>
#include <math.h>
#include <stdint.h>
#include <stddef.h>

#define B_SZ 32
#define T_SZ 256
#define D_SZ 2048
#define H_SZ 16
#define DK_SZ 64
#define NP   1024   /* H_SZ * DK_SZ */

// ---------------------------------------------------------------------------
// Device-global scratch (allocation-free rule: __device__ globals allowed)
// ---------------------------------------------------------------------------
__device__ float g_k[(size_t)B_SZ * T_SZ * NP];   // 32 MB : K projection (B*T, H*DK)
__device__ float g_v[(size_t)B_SZ * T_SZ * NP];   // 32 MB : V projection
__device__ float g_beta [B_SZ * H_SZ * T_SZ];     // (B*H, T)
__device__ float g_gamma[B_SZ * H_SZ * T_SZ];     // (B*H, T)

// ---------------------------------------------------------------------------
// Kernel 1: C = content @ W^T   M=8192, N=1024, K=2048 (fp32)
// blockIdx.z = 0 -> k_w -> g_k ; 1 -> v_w -> g_v
// 128x128 tile, BK=16, 256 threads, 8x8 microtile, double-buffered smem
// ---------------------------------------------------------------------------
#define BM  128
#define BN  128
#define BKK 16

__global__ __launch_bounds__(256) void gemm_proj(const float* __restrict__ A,
                                                 const float* __restrict__ Wk,
                                                 const float* __restrict__ Wv)
{
    const float* Bmat = blockIdx.z ? Wv : Wk;
    float*       C    = blockIdx.z ? g_v : g_k;
    const int bm = blockIdx.y * BM;
    const int bn = blockIdx.x * BN;

    __shared__ __align__(16) float As[2][BKK][BM + 4];   // padded rows (132 floats = 528B, 16B-mult)
    __shared__ __align__(16) float Bs[2][BKK][BN + 4];

    const int tid  = threadIdx.x;
    const int lrow = tid >> 2;          // 0..63
    const int lk4  = (tid & 3) * 4;     // 0,4,8,12
    const int tx   = tid & 15;
    const int ty   = tid >> 4;

    const float* Aptr = A    + (size_t)(bm + lrow) * D_SZ + lk4;
    const float* Bptr = Bmat + (size_t)(bn + lrow) * D_SZ + lk4;

    float acc[8][8] = {};

    float4 a0, a1, b0, b1;
    a0 = *(const float4*)(Aptr);
    a1 = *(const float4*)(Aptr + (size_t)64 * D_SZ);
    b0 = *(const float4*)(Bptr);
    b1 = *(const float4*)(Bptr + (size_t)64 * D_SZ);
#pragma unroll
    for (int q = 0; q < 4; ++q) {
        As[0][lk4 + q][lrow]      = ((const float*)&a0)[q];
        As[0][lk4 + q][lrow + 64] = ((const float*)&a1)[q];
        Bs[0][lk4 + q][lrow]      = ((const float*)&b0)[q];
        Bs[0][lk4 + q][lrow + 64] = ((const float*)&b1)[q];
    }
    __syncthreads();

    const int NT = D_SZ / BKK;   // 128
    for (int t = 0; t < NT; ++t) {
        const int cur = t & 1, nxt = cur ^ 1;
        if (t + 1 < NT) {
            const float* Ap = Aptr + (size_t)(t + 1) * BKK;
            const float* Bp = Bptr + (size_t)(t + 1) * BKK;
            a0 = *(const float4*)(Ap);
            a1 = *(const float4*)(Ap + (size_t)64 * D_SZ);
            b0 = *(const float4*)(Bp);
            b1 = *(const float4*)(Bp + (size_t)64 * D_SZ);
        }
#pragma unroll
        for (int kk = 0; kk < BKK; ++kk) {
            float af[8], bf[8];
            *(float4*)&af[0] = *(const float4*)&As[cur][kk][ty * 8];
            *(float4*)&af[4] = *(const float4*)&As[cur][kk][ty * 8 + 4];
            *(float4*)&bf[0] = *(const float4*)&Bs[cur][kk][tx * 8];
            *(float4*)&bf[4] = *(const float4*)&Bs[cur][kk][tx * 8 + 4];
#pragma unroll
            for (int i = 0; i < 8; ++i)
#pragma unroll
                for (int j = 0; j < 8; ++j)
                    acc[i][j] += af[i] * bf[j];
        }
        if (t + 1 < NT) {
#pragma unroll
            for (int q = 0; q < 4; ++q) {
                As[nxt][lk4 + q][lrow]      = ((const float*)&a0)[q];
                As[nxt][lk4 + q][lrow + 64] = ((const float*)&a1)[q];
                Bs[nxt][lk4 + q][lrow]      = ((const float*)&b0)[q];
                Bs[nxt][lk4 + q][lrow + 64] = ((const float*)&b1)[q];
            }
        }
        __syncthreads();
    }

#pragma unroll
    for (int i = 0; i < 8; ++i) {
        float* Crow = C + (size_t)(bm + ty * 8 + i) * NP + bn + tx * 8;
        *(float4*)(Crow)     = make_float4(acc[i][0], acc[i][1], acc[i][2], acc[i][3]);
        *(float4*)(Crow + 4) = make_float4(acc[i][4], acc[i][5], acc[i][6], acc[i][7]);
    }
}

// ---------------------------------------------------------------------------
// Kernel 2: beta / gamma   (8192 rows x 32 outputs; N=32 GEMM + sigmoid)
// one block per content row; thread = (out 0..31, seg 0..7); interleaved
// j*8+seg indexing -> conflict-free smem banks within a warp.
// ---------------------------------------------------------------------------
__global__ __launch_bounds__(256) void proj_small(const float* __restrict__ content,
                                                  const float* __restrict__ b_w,
                                                  const float* __restrict__ b_b,
                                                  const float* __restrict__ ts_w,
                                                  const float* __restrict__ ts_b,
                                                  const float* __restrict__ hd)
{
    __shared__ __align__(16) float row[D_SZ];
    const int r   = blockIdx.x;        // b*T + t
    const int tid = threadIdx.x;

    const float* src = content + (size_t)r * D_SZ;
#pragma unroll
    for (int i = 0; i < D_SZ / (256 * 4); ++i) {   // 2 iters
        float4 vv = *(const float4*)(src + i * 1024 + tid * 4);
        *(float4*)&row[i * 1024 + tid * 4] = vv;
    }
    __syncthreads();

    const int out = tid >> 3;          // 0..31
    const int seg = tid & 7;
    const float* w = (out < H_SZ) ? (b_w + (size_t)out * D_SZ)
                                  : (ts_w + (size_t)(out - H_SZ) * D_SZ);
    float acc = 0.f;
#pragma unroll 8
    for (int j = 0; j < D_SZ / 8; ++j) {
        const int idx = j * 8 + seg;
        acc += row[idx] * __ldg(&w[idx]);
    }
#pragma unroll
    for (int o = 4; o; o >>= 1) acc += __shfl_down_sync(0xffffffffu, acc, o);

    if (seg == 0) {
        const int b = r / T_SZ, t = r % T_SZ;
        if (out < H_SZ) {
            const float z = acc + b_b[out];
            g_beta[((size_t)b * H_SZ + out) * T_SZ + t] = 1.f / (1.f + expf(-z));
        } else {
            const int h = out - H_SZ;
            const float z  = acc + ts_b[h] + hd[h];
            const float gm = 1.f / (1.f + expf(-z));
            g_gamma[((size_t)b * H_SZ + h) * T_SZ + t] = fmaxf(gm, 1e-8f);
        }
    }
}

// ---------------------------------------------------------------------------
// Kernel 3: sequential gated delta-rule recurrence (exactly equals the
// reference's triangular solve):
//   k̂_t = k_t / max(||k_t||, 1e-12)
//   Vp_t = v_t - M k̂_t ;  M <- γ_t M + β_t Vp_t k̂_tᵀ ;  W_new = M_final
// grid = B*H (512), block = 64.  Thread v owns M[v][0:64] in registers.
// k/v staged in 16-step smem chunks; inner reads are float4 broadcasts.
// ---------------------------------------------------------------------------
#define CH 16
__global__ __launch_bounds__(64) void recurrence(const float* __restrict__ W_old,
                                                 float* __restrict__ W_new)
{
    const int bh   = blockIdx.x;
    const int b    = bh >> 4;
    const int h    = bh & 15;
    const int tid  = threadIdx.x;     // = v (value-dim row of M)
    const int lane = tid & 31;

    __shared__ __align__(16) float ksm[CH][64];
    __shared__ __align__(16) float vsm[CH][64];
    __shared__ float bsm[CH], gsm[CH];

    float M[64];
    const float* Wsrc = W_old + ((size_t)bh * DK_SZ + tid) * DK_SZ;
#pragma unroll
    for (int d4 = 0; d4 < 16; ++d4)
        *(float4*)&M[d4 * 4] = *(const float4*)(Wsrc + d4 * 4);

    const float* kbase = g_k + (size_t)b * T_SZ * NP + h * DK_SZ + tid;
    const float* vbase = g_v + (size_t)b * T_SZ * NP + h * DK_SZ + tid;
    const float* bb = g_beta  + (size_t)bh * T_SZ;
    const float* gg = g_gamma + (size_t)bh * T_SZ;

    for (int c = 0; c < T_SZ / CH; ++c) {
        __syncthreads();
#pragma unroll
        for (int rr = 0; rr < CH; ++rr) {
            const size_t off = (size_t)(c * CH + rr) * NP;
            ksm[rr][tid] = kbase[off];
            vsm[rr][tid] = vbase[off];
        }
        if (tid < CH) { bsm[tid] = bb[c * CH + tid]; gsm[tid] = gg[c * CH + tid]; }
        __syncthreads();

#pragma unroll 1
        for (int rr = 0; rr < CH; ++rr) {
            // ||k||^2 : each warp reduces the full 64 elems independently (no cross-warp sync)
            const float x0 = ksm[rr][lane], x1 = ksm[rr][lane + 32];
            float ss = x0 * x0 + x1 * x1;
#pragma unroll
            for (int o = 16; o; o >>= 1) ss += __shfl_xor_sync(0xffffffffu, ss, o);
            const float inv = 1.f / fmaxf(sqrtf(ss), 1e-12f);

            // dot = M[v][:] . k_raw   (thread-local; k broadcast from smem)
            float d0 = 0.f, d1 = 0.f, d2 = 0.f, d3 = 0.f;
#pragma unroll
            for (int d4 = 0; d4 < 16; ++d4) {
                const float4 kk4 = *(const float4*)&ksm[rr][d4 * 4];
                d0 += M[d4 * 4 + 0] * kk4.x;
                d1 += M[d4 * 4 + 1] * kk4.y;
                d2 += M[d4 * 4 + 2] * kk4.z;
                d3 += M[d4 * 4 + 3] * kk4.w;
            }
            const float dot = (d0 + d1) + (d2 + d3);
            const float vp  = vsm[rr][tid] - dot * inv;
            const float g   = gsm[rr];
            const float bvi = bsm[rr] * vp * inv;   // fold inv into the rank-1 update
#pragma unroll
            for (int d4 = 0; d4 < 16; ++d4) {
                const float4 kk4 = *(const float4*)&ksm[rr][d4 * 4];
                M[d4 * 4 + 0] = g * M[d4 * 4 + 0] + bvi * kk4.x;
                M[d4 * 4 + 1] = g * M[d4 * 4 + 1] + bvi * kk4.y;
                M[d4 * 4 + 2] = g * M[d4 * 4 + 2] + bvi * kk4.z;
                M[d4 * 4 + 3] = g * M[d4 * 4 + 3] + bvi * kk4.w;
            }
        }
    }

    float* Wdst = W_new + ((size_t)bh * DK_SZ + tid) * DK_SZ;
#pragma unroll
    for (int d4 = 0; d4 < 16; ++d4)
        *(float4*)(Wdst + d4 * 4) = *(const float4*)&M[d4 * 4];
}

// ---------------------------------------------------------------------------
// Launch (graph-capturable: kernel launches only, default stream ordering)
// Inputs (metadata order): W_old, content, k_w, v_w, b_w, b_b, ts_w, ts_b, hd_logits
// ---------------------------------------------------------------------------
extern "C" void kernel_launch(void* const* d_in, const int* in_sizes, int n_in,
                              void* d_out, int out_size)
{
    (void)in_sizes; (void)n_in; (void)out_size;
    const float* W_old   = (const float*)d_in[0];
    const float* content = (const float*)d_in[1];
    const float* k_w     = (const float*)d_in[2];
    const float* v_w     = (const float*)d_in[3];
    const float* b_w     = (const float*)d_in[4];
    const float* b_b     = (const float*)d_in[5];
    const float* ts_w    = (const float*)d_in[6];
    const float* ts_b    = (const float*)d_in[7];
    const float* hd      = (const float*)d_in[8];
    float* W_new = (float*)d_out;

    dim3 g1(NP / BN, (B_SZ * T_SZ) / BM, 2);       // (8, 64, 2)
    gemm_proj<<<g1, 256>>>(content, k_w, v_w);
    proj_small<<<B_SZ * T_SZ, 256>>>(content, b_w, b_b, ts_w, ts_b, hd);
    recurrence<<<B_SZ * H_SZ, 64>>>(W_old, W_new);
}